// round 1
// baseline (speedup 1.0000x reference)
#include <cuda_runtime.h>
#include <math_constants.h>

// Problem constants (B=128, L=4096, FILTER_SIZE=2, N_QUBITS=4, 10 classes)
#define OL   4095
#define OLP  4096   // padded
#define NCLS 10
#define B_SZ 128
#define NT   256

// Scratch for folded, transposed weights: Wp[j][ol] = K0*W[2ol,j] + K1*W[2ol+1,j]
// (no cudaMalloc allowed -> __device__ global)
__device__ __align__(16) float d_Wp[NCLS * OLP];

// ---------------------------------------------------------------------------
// Kernel 1: fold the two per-param-set constants K0,K1 into W, transposed.
// K_k = cos(p_k1)*cos(p_k2)*cos(p_k3)  (qubit 0 drops out of <Z1Z2Z3>)
// params flat layout: [p00,p01,p02,p03, p10,p11,p12,p13]
// ---------------------------------------------------------------------------
__global__ void qcnn_prep(const float* __restrict__ params,
                          const float* __restrict__ W)
{
    int ol = blockIdx.x * blockDim.x + threadIdx.x;
    if (ol >= OLP) return;
    float K0 = __cosf(params[1]) * __cosf(params[2]) * __cosf(params[3]);
    float K1 = __cosf(params[5]) * __cosf(params[6]) * __cosf(params[7]);
    if (ol < OL) {
#pragma unroll
        for (int j = 0; j < NCLS; ++j) {
            float w0 = W[(2 * ol)     * NCLS + j];
            float w1 = W[(2 * ol + 1) * NCLS + j];
            d_Wp[j * OLP + ol] = K0 * w0 + K1 * w1;
        }
    } else {
#pragma unroll
        for (int j = 0; j < NCLS; ++j)
            d_Wp[j * OLP + ol] = 0.0f;   // pad column 4095
    }
}

// ---------------------------------------------------------------------------
// Kernel 2: one block per batch row.
//   g(b,ol) = cos(x[b,ol,1]) * cos(x[b,ol+1,0]) * cos(x[b,ol+1,1])
//   logits[b,j] = bias[j] + sum_ol g(b,ol) * Wp[j][ol]
//   out[b,:]   = softmax(logits)
// ---------------------------------------------------------------------------
__global__ __launch_bounds__(NT) void qcnn_main(const float* __restrict__ x,
                                                const float* __restrict__ bias,
                                                float* __restrict__ out)
{
    __shared__ float sc0[OLP + 4];          // cos(x[.,0])
    __shared__ float sc1[OLP + 4];          // cos(x[.,1])
    __shared__ float sred[NT / 32][NCLS];   // per-warp partials

    const int b   = blockIdx.x;
    const int tid = threadIdx.x;

    // cos pass: coalesced float2 loads of the (4096,2) row
    const float2* row = (const float2*)(x + (size_t)b * OLP * 2);
    for (int i = tid; i < OLP; i += NT) {
        float2 v = row[i];
        sc0[i] = __cosf(v.x);
        sc1[i] = __cosf(v.y);
    }
    if (tid == 0) { sc0[OLP] = 0.0f; sc1[OLP] = 0.0f; }  // kill padded ol=4095
    __syncthreads();

    float acc[NCLS];
#pragma unroll
    for (int j = 0; j < NCLS; ++j) acc[j] = 0.0f;

    // 4096 padded windows, 4 per thread-iteration, 4 iterations total.
    // Wp loads are coalesced LDG.128 (L2-resident after prep).
    for (int base = tid * 4; base < OLP; base += NT * 4) {
        float a0 = sc1[base];
        float a1 = sc1[base + 1], b1 = sc0[base + 1];
        float a2 = sc1[base + 2], b2 = sc0[base + 2];
        float a3 = sc1[base + 3], b3 = sc0[base + 3];
        float a4 = sc1[base + 4], b4 = sc0[base + 4];
        float g0 = a0 * b1 * a1;
        float g1 = a1 * b2 * a2;
        float g2 = a2 * b3 * a3;
        float g3 = a3 * b4 * a4;
#pragma unroll
        for (int j = 0; j < NCLS; ++j) {
            float4 w = *(const float4*)(&d_Wp[j * OLP + base]);
            acc[j] = fmaf(g0, w.x, acc[j]);
            acc[j] = fmaf(g1, w.y, acc[j]);
            acc[j] = fmaf(g2, w.z, acc[j]);
            acc[j] = fmaf(g3, w.w, acc[j]);
        }
    }

    // intra-warp reduction of the 10 accumulators
#pragma unroll
    for (int j = 0; j < NCLS; ++j) {
#pragma unroll
        for (int off = 16; off; off >>= 1)
            acc[j] += __shfl_xor_sync(0xFFFFFFFFu, acc[j], off);
    }
    const int warp = tid >> 5, lane = tid & 31;
    if (lane == 0) {
#pragma unroll
        for (int j = 0; j < NCLS; ++j) sred[warp][j] = acc[j];
    }
    __syncthreads();

    // final reduce + softmax in the first warp (lanes 0..9 own one class each)
    if (tid < 32) {
        float logit = -CUDART_INF_F;
        if (tid < NCLS) {
            logit = bias[tid];
#pragma unroll
            for (int w = 0; w < NT / 32; ++w) logit += sred[w][tid];
        }
        float mx = logit;
#pragma unroll
        for (int off = 16; off; off >>= 1)
            mx = fmaxf(mx, __shfl_xor_sync(0xFFFFFFFFu, mx, off));
        float e = (tid < NCLS) ? __expf(logit - mx) : 0.0f;
        float s = e;
#pragma unroll
        for (int off = 16; off; off >>= 1)
            s += __shfl_xor_sync(0xFFFFFFFFu, s, off);
        if (tid < NCLS) out[b * NCLS + tid] = e / s;
    }
}

// ---------------------------------------------------------------------------
// Inputs (metadata order): inputs(128*4096*2 f32), params(8 f32),
//                          W(8190*10 f32), b(10 f32). Output: (128*10) f32.
// ---------------------------------------------------------------------------
extern "C" void kernel_launch(void* const* d_in, const int* in_sizes, int n_in,
                              void* d_out, int out_size)
{
    const float* inputs = (const float*)d_in[0];
    const float* params = (const float*)d_in[1];
    const float* W      = (const float*)d_in[2];
    const float* bias   = (const float*)d_in[3];
    float* out          = (float*)d_out;

    qcnn_prep<<<OLP / NT, NT>>>(params, W);
    qcnn_main<<<B_SZ, NT>>>(inputs, bias, out);
}

// round 2
// speedup vs baseline: 1.3206x; 1.3206x over previous
#include <cuda_runtime.h>
#include <math_constants.h>

// Problem constants (B=128, L=4096, FILTER_SIZE=2, N_QUBITS=4, 10 classes)
#define OL    4095
#define OLP   4096          // padded window count
#define NCLS  10
#define B_SZ  128
#define NT    1024
#define NWARP (NT / 32)

// Folded, transposed weights: Wp[j][ol] = K0*W[2ol,j] + K1*W[2ol+1,j]
__device__ __align__(16) float d_Wp[NCLS * OLP];

// ---------------------------------------------------------------------------
// Kernel 1: fold per-param-set constants K_k = cos(p_k1)cos(p_k2)cos(p_k3)
// (qubit 0 drops out: CNOT ring conjugates Z0 -> Z1Z2Z3) into W, transposed.
// ---------------------------------------------------------------------------
__global__ void qcnn_prep(const float* __restrict__ params,
                          const float* __restrict__ W)
{
    int ol = blockIdx.x * blockDim.x + threadIdx.x;
    if (ol >= OLP) return;
    float K0 = __cosf(params[1]) * __cosf(params[2]) * __cosf(params[3]);
    float K1 = __cosf(params[5]) * __cosf(params[6]) * __cosf(params[7]);
    if (ol < OL) {
#pragma unroll
        for (int j = 0; j < NCLS; ++j) {
            float w0 = W[(2 * ol)     * NCLS + j];   // L1-cached (80B/ol reused over j)
            float w1 = W[(2 * ol + 1) * NCLS + j];
            d_Wp[j * OLP + ol] = K0 * w0 + K1 * w1;
        }
    } else {
#pragma unroll
        for (int j = 0; j < NCLS; ++j)
            d_Wp[j * OLP + ol] = 0.0f;               // pad column 4095
    }
}

// ---------------------------------------------------------------------------
// Kernel 2: one block (1024 threads) per batch row.
//   g(ol) = cos(x[ol,1]) * cos(x[ol+1,0]) * cos(x[ol+1,1]) = s1[ol]*h[ol+1]
//   logits[j] = bias[j] + sum_ol g(ol) * Wp[j][ol]  ->  softmax
// smem holds interleaved (s1, h) pairs so the dot phase is 3 LDS.128/thread.
// ---------------------------------------------------------------------------
__global__ __launch_bounds__(NT, 1) void qcnn_main(const float* __restrict__ x,
                                                   const float* __restrict__ bias,
                                                   float* __restrict__ out)
{
    __shared__ __align__(16) float2 sc[OLP + 4];     // sc[i] = (s1[i], h[i])
    __shared__ float sred[NWARP][NCLS];

    const int b   = blockIdx.x;
    const int tid = threadIdx.x;

    // --- cos pass: float4 = 2 input elements; one STS.128 per float4 ---
    const float4* row4 = (const float4*)(x + (size_t)b * OLP * 2);
#pragma unroll
    for (int k = 0; k < 2; ++k) {
        int i = tid + k * NT;                        // 0..2047 (covers 4096 elems)
        float4 v = row4[i];
        float c1a = __cosf(v.y), h_a = __cosf(v.x) * c1a;
        float c1b = __cosf(v.w), h_b = __cosf(v.z) * c1b;
        *(float4*)&sc[2 * i] = make_float4(c1a, h_a, c1b, h_b);
    }
    if (tid < 4) sc[OLP + tid] = make_float2(0.0f, 0.0f);  // kill padded ol=4095
    __syncthreads();

    // --- dot phase: 4 consecutive windows per thread, no loop ---
    const int base = tid * 4;
    float4 A = *(const float4*)&sc[base];            // s1[b],h[b],s1[b+1],h[b+1]
    float4 Bv = *(const float4*)&sc[base + 2];       // s1[b+2],h[b+2],s1[b+3],h[b+3]
    float4 C = *(const float4*)&sc[base + 4];        // s1[b+4],h[b+4],...
    float g0 = A.x  * A.w;
    float g1 = A.z  * Bv.y;
    float g2 = Bv.x * Bv.w;
    float g3 = Bv.z * C.y;

    float acc[NCLS];
#pragma unroll
    for (int j = 0; j < NCLS; ++j) {
        float4 w = *(const float4*)(&d_Wp[j * OLP + base]);   // coalesced, L2-hot
        float a;
        a = g0 * w.x;
        a = fmaf(g1, w.y, a);
        a = fmaf(g2, w.z, a);
        a = fmaf(g3, w.w, a);
        acc[j] = a;
    }

    // --- reduce 1024 threads -> 10 logits ---
#pragma unroll
    for (int j = 0; j < NCLS; ++j) {
#pragma unroll
        for (int off = 16; off; off >>= 1)
            acc[j] += __shfl_xor_sync(0xFFFFFFFFu, acc[j], off);
    }
    const int warp = tid >> 5, lane = tid & 31;
    if (lane == 0) {
#pragma unroll
        for (int j = 0; j < NCLS; ++j) sred[warp][j] = acc[j];
    }
    __syncthreads();

    // --- final reduce + softmax in warp 0 (lanes 0..9 own one class) ---
    if (tid < 32) {
        float logit = -CUDART_INF_F;
        if (tid < NCLS) {
            logit = bias[tid];
#pragma unroll
            for (int w = 0; w < NWARP; ++w) logit += sred[w][tid];
        }
        float mx = logit;
#pragma unroll
        for (int off = 16; off; off >>= 1)
            mx = fmaxf(mx, __shfl_xor_sync(0xFFFFFFFFu, mx, off));
        float e = (tid < NCLS) ? __expf(logit - mx) : 0.0f;
        float s = e;
#pragma unroll
        for (int off = 16; off; off >>= 1)
            s += __shfl_xor_sync(0xFFFFFFFFu, s, off);
        if (tid < NCLS) out[b * NCLS + tid] = e / s;
    }
}

// ---------------------------------------------------------------------------
// Inputs (metadata order): inputs(128*4096*2 f32), params(8 f32),
//                          W(8190*10 f32), b(10 f32). Output: (128*10) f32.
// ---------------------------------------------------------------------------
extern "C" void kernel_launch(void* const* d_in, const int* in_sizes, int n_in,
                              void* d_out, int out_size)
{
    const float* inputs = (const float*)d_in[0];
    const float* params = (const float*)d_in[1];
    const float* W      = (const float*)d_in[2];
    const float* bias   = (const float*)d_in[3];
    float* out          = (float*)d_out;

    qcnn_prep<<<OLP / 256, 256>>>(params, W);
    qcnn_main<<<B_SZ, NT>>>(inputs, bias, out);
}